// round 3
// baseline (speedup 1.0000x reference)
#include <cuda_runtime.h>
#include <cstdint>

#define DMODEL 2048
#define NB 144
#define BM 16
#define BK 16
#define BSTRIDE 20   // 16 data floats + 4 pad per smem row
#define KT_STEPS (DMODEL / BK)   // 128

// Scratch: S[N][144] = [s1 | s2 | qg] per token
__device__ float g_S[16384 * NB];

__device__ __forceinline__ void cp16(void* s, const void* g) {
  unsigned saddr = (unsigned)__cvta_generic_to_shared(s);
  asm volatile("cp.async.cg.shared.global [%0], [%1], 16;" :: "r"(saddr), "l"(g));
}

// ---------------------------------------------------------------------------
// Kernel 1: skinny GEMM  S = x @ [W1|W2|Wg]^T   fp32 via packed f32x2 FMA
// BM=16 tokens per 32-thread CTA, grid=1024 (98.9% SM util at occ 8),
// cp.async double-buffered tiles.
// ---------------------------------------------------------------------------
__global__ __launch_bounds__(32, 8) void pk_gemm(
    const float* __restrict__ x, const float* __restrict__ W1,
    const float* __restrict__ W2, const float* __restrict__ Wg) {
  __shared__ __align__(16) float a_s[2][BM][BSTRIDE];
  __shared__ __align__(16) float b_s[2][NB][BSTRIDE];

  const int tid = threadIdx.x;
  const int tx = tid & 15;          // n-dim: 16 groups of 9 cols
  const int ty = tid >> 4;          // m-dim: 2 groups of 8 rows
  const int n0 = tx * 9;
  const int m0 = ty * 8;
  const int tbase = blockIdx.x * BM;

  const int fo = (tid & 3) * 4;     // float offset of this thread's 16B chunk
  const int nr = tid >> 2;          // base row for loads (0..7)

  // Per-thread global base pointers for the 18 B-chunks + 2 A-chunks
  const float* bsrc[18];
#pragma unroll
  for (int j = 0; j < 18; j++) {
    const int n = nr + 8 * j;
    bsrc[j] = ((j < 8)  ? (W1 + (size_t)n * DMODEL)
             : (j < 16) ? (W2 + (size_t)(n - 64) * DMODEL)
                        : (Wg + (size_t)(n - 128) * DMODEL)) + fo;
  }
  const float* asrc0 = x + (size_t)(tbase + nr) * DMODEL + fo;
  const float* asrc1 = x + (size_t)(tbase + nr + 8) * DMODEL + fo;

  unsigned long long acc[4][9];
#pragma unroll
  for (int p = 0; p < 4; p++)
#pragma unroll
    for (int j = 0; j < 9; j++) acc[p][j] = 0ull;

  auto load_stage = [&](int kt, int s) {
    const int koff = kt * BK;
#pragma unroll
    for (int j = 0; j < 18; j++)
      cp16(&b_s[s][nr + 8 * j][fo], bsrc[j] + koff);
    cp16(&a_s[s][nr][fo], asrc0 + koff);
    cp16(&a_s[s][nr + 8][fo], asrc1 + koff);
    asm volatile("cp.async.commit_group;" ::: "memory");
  };

  load_stage(0, 0);
  load_stage(1, 1);

  for (int kt = 0; kt < KT_STEPS; kt++) {
    const int s = kt & 1;
    asm volatile("cp.async.wait_group 1;" ::: "memory");
    __syncwarp();

    // compute stage s: 16 k-steps
#pragma unroll
    for (int k4 = 0; k4 < 4; k4++) {
      float4 b4[9];
#pragma unroll
      for (int j = 0; j < 9; j++)
        b4[j] = *(const float4*)&b_s[s][n0 + j][k4 * 4];
#pragma unroll
      for (int u = 0; u < 4; u++) {
        const int kk = k4 * 4 + u;
        unsigned long long a2[4];
#pragma unroll
        for (int p = 0; p < 4; p++) {
          float alo = a_s[s][m0 + 2 * p][kk];
          float ahi = a_s[s][m0 + 2 * p + 1][kk];
          asm("mov.b64 %0, {%1, %2};" : "=l"(a2[p]) : "f"(alo), "f"(ahi));
        }
#pragma unroll
        for (int j = 0; j < 9; j++) {
          const float bv = (&b4[j].x)[u];
          unsigned long long b2;
          asm("mov.b64 %0, {%1, %1};" : "=l"(b2) : "f"(bv));
#pragma unroll
          for (int p = 0; p < 4; p++)
            asm("fma.rn.f32x2 %0, %1, %2, %0;"
                : "+l"(acc[p][j]) : "l"(a2[p]), "l"(b2));
        }
      }
    }
    __syncwarp();   // all lanes done reading stage s before overwrite

    if (kt + 2 < KT_STEPS) load_stage(kt + 2, s);
  }

  // epilogue
#pragma unroll
  for (int p = 0; p < 4; p++) {
    const int mg = tbase + m0 + 2 * p;
#pragma unroll
    for (int j = 0; j < 9; j++) {
      unsigned long long v = acc[p][j];
      g_S[(size_t)mg * NB + n0 + j] = __uint_as_float((unsigned)v);
      g_S[(size_t)(mg + 1) * NB + n0 + j] = __uint_as_float((unsigned)(v >> 32));
    }
  }
}

// ---------------------------------------------------------------------------
// Kernel 2: fused expand (256MB streaming write) + top-8 + gate + softmax.
// One block per token. Thread 0 does the serial topk while 128 threads
// stream the 16KB expand row; serial latency hides under store pressure.
// ---------------------------------------------------------------------------
__device__ __forceinline__ void insert8(float v, int idx, float* vals, int* idxs) {
  if (v < vals[7] || (v == vals[7] && idx >= idxs[7])) return;
  int p = 7;
  while (p > 0 && (v > vals[p - 1] || (v == vals[p - 1] && idx < idxs[p - 1]))) {
    vals[p] = vals[p - 1]; idxs[p] = idxs[p - 1]; --p;
  }
  vals[p] = v; idxs[p] = idx;
}

__global__ __launch_bounds__(128) void pk_finish(
    const float* __restrict__ G,
    float* __restrict__ out_idx, float* __restrict__ out_w,
    float4* __restrict__ out_sc) {
  __shared__ __align__(16) float row[160];
  const int tid = threadIdx.x;
  const int tok = blockIdx.x;

  if (tid < NB / 4)
    ((float4*)row)[tid] = ((const float4*)(g_S + (size_t)tok * NB))[tid];
  __syncthreads();

  // expand: row-contiguous streaming stores, 8 float4 per thread
  float4* dst = out_sc + (size_t)tok * 1024;
#pragma unroll
  for (int r = 0; r < 8; r++) {
    const int i = tid + 128 * r;
    const int a = i >> 4;
    const int b4 = i & 15;
    const float s1 = row[a];
    const float4 s2 = *(const float4*)&row[64 + b4 * 4];
    __stcs(dst + i, make_float4(s1 + s2.x, s1 + s2.y, s1 + s2.z, s1 + s2.w));
  }

  if (tid == 0) {
    float v1[8], v2[8], cv[8];
    int i1[8], i2[8], ci[8];
#pragma unroll
    for (int t = 0; t < 8; t++) {
      v1[t] = v2[t] = cv[t] = -3.4e38f;
      i1[t] = i2[t] = ci[t] = 0x7fffffff;
    }
    for (int a = 0; a < 64; a++) insert8(row[a], a, v1, i1);
    for (int b = 0; b < 64; b++) insert8(row[64 + b], b, v2, i2);
    for (int ai = 0; ai < 8; ai++)
      for (int bi = 0; bi < 8; bi++)
        insert8(v1[ai] + v2[bi], i1[ai] * 64 + i2[bi], cv, ci);

    float comb[8];
    for (int t = 0; t < 8; t++) {
      const float4* grow = (const float4*)(G + (size_t)ci[t] * 16);
      float g = 0.f;
#pragma unroll
      for (int u = 0; u < 4; u++) {
        float4 gv = grow[u];
        const float* q = row + 128 + u * 4;
        g += q[0] * gv.x + q[1] * gv.y + q[2] * gv.z + q[3] * gv.w;
      }
      comb[t] = cv[t] + g;
    }
    float mx = comb[0];
    for (int t = 1; t < 8; t++) mx = fmaxf(mx, comb[t]);
    float e[8], sum = 0.f;
    for (int t = 0; t < 8; t++) { e[t] = expf(comb[t] - mx); sum += e[t]; }
    const float inv = 1.f / sum;
    for (int t = 0; t < 8; t++) {
      out_idx[(size_t)tok * 8 + t] = (float)ci[t];
      out_w[(size_t)tok * 8 + t] = e[t] * inv;
    }
  }
}

// ---------------------------------------------------------------------------
extern "C" void kernel_launch(void* const* d_in, const int* in_sizes, int n_in,
                              void* d_out, int out_size) {
  const float* x  = (const float*)d_in[0];
  const float* W1 = (const float*)d_in[1];
  const float* W2 = (const float*)d_in[2];
  const float* Wg = (const float*)d_in[3];
  const float* G  = (const float*)d_in[4];
  float* out = (float*)d_out;

  const int Ntok = in_sizes[0] / DMODEL;   // 16384

  float* out_idx = out;
  float* out_w   = out + (size_t)Ntok * 8;
  float* out_sc  = out + (size_t)Ntok * 16;

  pk_gemm<<<Ntok / BM, 32>>>(x, W1, W2, Wg);
  pk_finish<<<Ntok, 128>>>(G, out_idx, out_w, (float4*)out_sc);
}